// round 12
// baseline (speedup 1.0000x reference)
#include <cuda_runtime.h>

#define N_NODES 100000
#define N_EDGES 3200000
#define D_IN    256
#define D_OUT   128
#define LN_EPS  1e-5f

#define BM 64
#define BK 32

// ---------------- static device scratch (no runtime allocation) ----------------
__device__ float g_support[(size_t)N_NODES * D_OUT];   // x @ W
__device__ float g_base[(size_t)N_NODES * D_OUT];      // bias + relu(x @ res_w + res_b)
__device__ int   g_count[N_NODES];
__device__ int   g_offsets[N_NODES];
__device__ int   g_cursor[N_NODES];
__device__ int   g_perm[N_EDGES];
__device__ int   g_partials[128];

// ---------------- f32x2 packed-math helpers (FFMA2 path) ----------------
__device__ __forceinline__ unsigned long long dup2(float a) {
    unsigned long long r;
    unsigned int ai = __float_as_uint(a);
    asm("mov.b64 %0, {%1, %1};" : "=l"(r) : "r"(ai));
    return r;
}
__device__ __forceinline__ void fma2(unsigned long long& d, unsigned long long a,
                                     unsigned long long b) {
    asm("fma.rn.f32x2 %0, %1, %2, %0;" : "+l"(d) : "l"(a), "l"(b));
}
__device__ __forceinline__ float2 unpack2(unsigned long long v) {
    unsigned int lo, hi;
    asm("mov.b64 {%0, %1}, %2;" : "=r"(lo), "=r"(hi) : "l"(v));
    float2 r;
    r.x = __uint_as_float(lo);
    r.y = __uint_as_float(hi);
    return r;
}

// ---------------- kernel 1: fused dual GEMM ----------------
// support[n,:] = x[n,:] @ W          (D_IN x D_OUT)
// base[n,:]    = bias + relu(x[n,:] @ Rw + resb)
__global__ void __launch_bounds__(256, 2)
k_gemm(const float* __restrict__ x, const float* __restrict__ W,
       const float* __restrict__ Rw, const float* __restrict__ bias,
       const float* __restrict__ resb) {
    __shared__ float xs[BM][BK + 1];
    __shared__ __align__(16) float ws[BK][D_OUT];
    __shared__ __align__(16) float rs[BK][D_OUT];

    const int tid = threadIdx.x;          // 256 threads
    const int tx  = tid & 15;             // column group: cols tx*8 .. tx*8+7
    const int ty  = tid >> 4;             // rows ty + 16*i, i=0..3
    const int rowBase = blockIdx.x * BM;

    unsigned long long accW[4][4], accR[4][4];
#pragma unroll
    for (int i = 0; i < 4; i++)
#pragma unroll
        for (int j = 0; j < 4; j++) { accW[i][j] = 0ull; accR[i][j] = 0ull; }

    for (int k0 = 0; k0 < D_IN; k0 += BK) {
        // load x tile 64x32 (512 float4 -> 2 per thread), guard tail rows
#pragma unroll
        for (int f = tid; f < BM * BK / 4; f += 256) {
            int r = f >> 3;
            int c = (f & 7) * 4;
            float4 v = make_float4(0.f, 0.f, 0.f, 0.f);
            int row = rowBase + r;
            if (row < N_NODES)
                v = *(const float4*)(x + (size_t)row * D_IN + k0 + c);
            xs[r][c + 0] = v.x; xs[r][c + 1] = v.y;
            xs[r][c + 2] = v.z; xs[r][c + 3] = v.w;
        }
        // load W,R tiles 32x128 (1024 float4 each -> 4 per thread)
#pragma unroll
        for (int f = tid; f < BK * D_OUT / 4; f += 256) {
            int r = f >> 5;
            int c = (f & 31) * 4;
            *(float4*)&ws[r][c] = *(const float4*)(W  + (size_t)(k0 + r) * D_OUT + c);
            *(float4*)&rs[r][c] = *(const float4*)(Rw + (size_t)(k0 + r) * D_OUT + c);
        }
        __syncthreads();

#pragma unroll 8
        for (int k = 0; k < BK; k++) {
            unsigned long long a2[4];
#pragma unroll
            for (int i = 0; i < 4; i++) a2[i] = dup2(xs[ty + 16 * i][k]);
            // conflict-free LDS.128: 16 distinct 32B-aligned addresses per warp
            ulonglong2 w0 = *(const ulonglong2*)&ws[k][tx * 8];
            ulonglong2 w1 = *(const ulonglong2*)&ws[k][tx * 8 + 4];
            ulonglong2 r0 = *(const ulonglong2*)&rs[k][tx * 8];
            ulonglong2 r1 = *(const ulonglong2*)&rs[k][tx * 8 + 4];
#pragma unroll
            for (int i = 0; i < 4; i++) {
                fma2(accW[i][0], a2[i], w0.x);
                fma2(accW[i][1], a2[i], w0.y);
                fma2(accW[i][2], a2[i], w1.x);
                fma2(accW[i][3], a2[i], w1.y);
                fma2(accR[i][0], a2[i], r0.x);
                fma2(accR[i][1], a2[i], r0.y);
                fma2(accR[i][2], a2[i], r1.x);
                fma2(accR[i][3], a2[i], r1.y);
            }
        }
        __syncthreads();
    }

    // epilogue
    const float4 b0  = *(const float4*)(bias + tx * 8);
    const float4 b1  = *(const float4*)(bias + tx * 8 + 4);
    const float4 rb0 = *(const float4*)(resb + tx * 8);
    const float4 rb1 = *(const float4*)(resb + tx * 8 + 4);
#pragma unroll
    for (int i = 0; i < 4; i++) {
        int row = rowBase + ty + 16 * i;
        if (row >= N_NODES) continue;
        float2 s0 = unpack2(accW[i][0]), s1 = unpack2(accW[i][1]);
        float2 s2 = unpack2(accW[i][2]), s3 = unpack2(accW[i][3]);
        float2 t0 = unpack2(accR[i][0]), t1 = unpack2(accR[i][1]);
        float2 t2 = unpack2(accR[i][2]), t3 = unpack2(accR[i][3]);

        float* supp = g_support + (size_t)row * D_OUT + tx * 8;
        *(float4*)(supp)     = make_float4(s0.x, s0.y, s1.x, s1.y);
        *(float4*)(supp + 4) = make_float4(s2.x, s2.y, s3.x, s3.y);

        float* bp = g_base + (size_t)row * D_OUT + tx * 8;
        float4 bv0, bv1;
        bv0.x = b0.x + fmaxf(t0.x + rb0.x, 0.f);
        bv0.y = b0.y + fmaxf(t0.y + rb0.y, 0.f);
        bv0.z = b0.z + fmaxf(t1.x + rb0.z, 0.f);
        bv0.w = b0.w + fmaxf(t1.y + rb0.w, 0.f);
        bv1.x = b1.x + fmaxf(t2.x + rb1.x, 0.f);
        bv1.y = b1.y + fmaxf(t2.y + rb1.y, 0.f);
        bv1.z = b1.z + fmaxf(t3.x + rb1.z, 0.f);
        bv1.w = b1.w + fmaxf(t3.y + rb1.w, 0.f);
        *(float4*)(bp)     = bv0;
        *(float4*)(bp + 4) = bv1;
    }
}

// ---------------- counting sort pipeline ----------------
__global__ void k_zero_count() {
    int i = blockIdx.x * blockDim.x + threadIdx.x;
    if (i < N_NODES) g_count[i] = 0;
}

__global__ void k_hist(const int* __restrict__ dst) {
    int e = blockIdx.x * blockDim.x + threadIdx.x;
    if (e < N_EDGES) atomicAdd(&g_count[dst[e]], 1);
}

__global__ void k_scan1() {  // per-block exclusive scan, 98 blocks x 1024
    __shared__ int s[1024];
    int i = blockIdx.x * 1024 + threadIdx.x;
    int v = (i < N_NODES) ? g_count[i] : 0;
    s[threadIdx.x] = v;
    __syncthreads();
#pragma unroll
    for (int off = 1; off < 1024; off <<= 1) {
        int t = (threadIdx.x >= off) ? s[threadIdx.x - off] : 0;
        __syncthreads();
        s[threadIdx.x] += t;
        __syncthreads();
    }
    if (i < N_NODES) g_offsets[i] = s[threadIdx.x] - v;   // exclusive
    if (threadIdx.x == 1023) g_partials[blockIdx.x] = s[1023];
}

__global__ void k_scan2() {  // single block scans 98 partials (128 threads)
    __shared__ int s[128];
    int nblk = (N_NODES + 1023) / 1024;   // 98
    int v = (threadIdx.x < nblk) ? g_partials[threadIdx.x] : 0;
    s[threadIdx.x] = v;
    __syncthreads();
#pragma unroll
    for (int off = 1; off < 128; off <<= 1) {
        int t = (threadIdx.x >= off) ? s[threadIdx.x - off] : 0;
        __syncthreads();
        s[threadIdx.x] += t;
        __syncthreads();
    }
    g_partials[threadIdx.x] = s[threadIdx.x] - v;         // exclusive
}

__global__ void k_scan3() {  // add block prefixes; init cursor
    int i = blockIdx.x * 1024 + threadIdx.x;
    if (i < N_NODES) {
        int o = g_offsets[i] + g_partials[blockIdx.x];
        g_offsets[i] = o;
        g_cursor[i]  = o;
    }
}

__global__ void k_scatter(const int* __restrict__ dst) {
    int e = blockIdx.x * blockDim.x + threadIdx.x;
    if (e < N_EDGES) {
        int d = dst[e];
        int p = atomicAdd(&g_cursor[d], 1);
        g_perm[p] = e;
    }
}

// ---------------- kernel: gather-aggregate + residual + LayerNorm ----------------
// one warp per node, 4 features per lane (float4)
__global__ void __launch_bounds__(256)
k_agg(const int* __restrict__ esrc, const float* __restrict__ ew,
      const float* __restrict__ gamma, const float* __restrict__ beta,
      float* __restrict__ out) {
    int gwarp = (blockIdx.x * blockDim.x + threadIdx.x) >> 5;
    int lane  = threadIdx.x & 31;
    if (gwarp >= N_NODES) return;
    const int n = gwarp;

    const int start = g_offsets[n];
    const int end   = (n == N_NODES - 1) ? N_EDGES : g_offsets[n + 1];

    const float4* __restrict__ sup4 = (const float4*)g_support;
    float4 acc = ((const float4*)g_base)[(size_t)n * 32 + lane];

    for (int b = start; b < end; b += 32) {
        int e = b + lane;
        int s = 0; float w = 0.f;
        if (e < end) {
            int idx = g_perm[e];
            s = esrc[idx];
            w = ew[idx];
        }
        int cnt = min(32, end - b);
        if (cnt == 32) {
#pragma unroll 8
            for (int it = 0; it < 32; it++) {
                int   ss = __shfl_sync(0xffffffffu, s, it);
                float ww = __shfl_sync(0xffffffffu, w, it);
                float4 v = sup4[(size_t)ss * 32 + lane];
                acc.x = fmaf(ww, v.x, acc.x);
                acc.y = fmaf(ww, v.y, acc.y);
                acc.z = fmaf(ww, v.z, acc.z);
                acc.w = fmaf(ww, v.w, acc.w);
            }
        } else {
            for (int it = 0; it < cnt; it++) {
                int   ss = __shfl_sync(0xffffffffu, s, it);
                float ww = __shfl_sync(0xffffffffu, w, it);
                float4 v = sup4[(size_t)ss * 32 + lane];
                acc.x = fmaf(ww, v.x, acc.x);
                acc.y = fmaf(ww, v.y, acc.y);
                acc.z = fmaf(ww, v.z, acc.z);
                acc.w = fmaf(ww, v.w, acc.w);
            }
        }
    }

    // LayerNorm over 128 features (warp reduction)
    float psum = acc.x + acc.y + acc.z + acc.w;
#pragma unroll
    for (int o = 16; o; o >>= 1) psum += __shfl_xor_sync(0xffffffffu, psum, o);
    float mu = psum * (1.f / 128.f);

    float dx = acc.x - mu, dy = acc.y - mu, dz = acc.z - mu, dw = acc.w - mu;
    float pv = dx * dx + dy * dy + dz * dz + dw * dw;
#pragma unroll
    for (int o = 16; o; o >>= 1) pv += __shfl_xor_sync(0xffffffffu, pv, o);
    float rstd = rsqrtf(pv * (1.f / 128.f) + LN_EPS);

    float4 g  = ((const float4*)gamma)[lane];
    float4 bt = ((const float4*)beta)[lane];
    float4 o4;
    o4.x = dx * rstd * g.x + bt.x;
    o4.y = dy * rstd * g.y + bt.y;
    o4.z = dz * rstd * g.z + bt.z;
    o4.w = dw * rstd * g.w + bt.w;
    ((float4*)out)[(size_t)n * 32 + lane] = o4;
}

// ---------------- launcher ----------------
extern "C" void kernel_launch(void* const* d_in, const int* in_sizes, int n_in,
                              void* d_out, int out_size) {
    const float* x      = (const float*)d_in[0];
    const float* weight = (const float*)d_in[1];
    const float* bias   = (const float*)d_in[2];
    const float* res_w  = (const float*)d_in[3];
    const float* res_b  = (const float*)d_in[4];
    const float* gamma  = (const float*)d_in[5];
    const float* beta   = (const float*)d_in[6];
    const float* ew     = (const float*)d_in[7];
    const int*   eidx   = (const int*)d_in[8];
    const int* esrc = eidx;
    const int* edst = eidx + N_EDGES;
    float* out = (float*)d_out;

    const int nScanBlk = (N_NODES + 1023) / 1024;   // 98

    k_zero_count<<<(N_NODES + 1023) / 1024, 1024>>>();
    k_gemm<<<(N_NODES + BM - 1) / BM, 256>>>(x, weight, res_w, bias, res_b);
    k_hist<<<(N_EDGES + 255) / 256, 256>>>(edst);
    k_scan1<<<nScanBlk, 1024>>>();
    k_scan2<<<1, 128>>>();
    k_scan3<<<nScanBlk, 1024>>>();
    k_scatter<<<(N_EDGES + 255) / 256, 256>>>(edst);
    k_agg<<<(N_NODES * 32 + 255) / 256, 256>>>(esrc, ew, gamma, beta, out);
}

// round 13
// speedup vs baseline: 1.5142x; 1.5142x over previous
#include <cuda_runtime.h>

#define N_NODES 100000
#define N_EDGES 3200000
#define D_IN    256
#define D_OUT   128
#define LN_EPS  1e-5f

#define BM 64
#define BK 32

// ---------------- static device scratch (no runtime allocation) ----------------
__device__ float g_support[(size_t)N_NODES * D_OUT];   // x @ W
__device__ float g_base[(size_t)N_NODES * D_OUT];      // bias + relu(x @ res_w + res_b)
__device__ int   g_count[N_NODES];
__device__ int   g_offsets[N_NODES];
__device__ int   g_cursor[N_NODES];
__device__ int   g_perm[N_EDGES];
__device__ int   g_partials[128];

// ---------------- f32x2 packed-math helpers (FFMA2 path) ----------------
__device__ __forceinline__ unsigned long long dup2(float a) {
    unsigned long long r;
    unsigned int ai = __float_as_uint(a);
    asm("mov.b64 %0, {%1, %1};" : "=l"(r) : "r"(ai));
    return r;
}
__device__ __forceinline__ void fma2(unsigned long long& d, unsigned long long a,
                                     unsigned long long b) {
    asm("fma.rn.f32x2 %0, %1, %2, %0;" : "+l"(d) : "l"(a), "l"(b));
}
__device__ __forceinline__ float2 unpack2(unsigned long long v) {
    unsigned int lo, hi;
    asm("mov.b64 {%0, %1}, %2;" : "=r"(lo), "=r"(hi) : "l"(v));
    float2 r;
    r.x = __uint_as_float(lo);
    r.y = __uint_as_float(hi);
    return r;
}

// ---------------- kernel 1: fused dual GEMM ----------------
// support[n,:] = x[n,:] @ W          (D_IN x D_OUT)
// base[n,:]    = bias + relu(x[n,:] @ Rw + resb)
__global__ void __launch_bounds__(256, 2)
k_gemm(const float* __restrict__ x, const float* __restrict__ W,
       const float* __restrict__ Rw, const float* __restrict__ bias,
       const float* __restrict__ resb) {
    __shared__ float xs[BM][BK + 1];
    __shared__ __align__(16) float ws[BK][D_OUT];
    __shared__ __align__(16) float rs[BK][D_OUT];

    const int tid = threadIdx.x;          // 256 threads
    const int tx  = tid & 15;             // column group: cols tx*8 .. tx*8+7
    const int ty  = tid >> 4;             // rows ty + 16*i, i=0..3
    const int rowBase = blockIdx.x * BM;

    unsigned long long accW[4][4], accR[4][4];
#pragma unroll
    for (int i = 0; i < 4; i++)
#pragma unroll
        for (int j = 0; j < 4; j++) { accW[i][j] = 0ull; accR[i][j] = 0ull; }

    for (int k0 = 0; k0 < D_IN; k0 += BK) {
        // load x tile 64x32 (512 float4 -> 2 per thread), guard tail rows
#pragma unroll
        for (int f = tid; f < BM * BK / 4; f += 256) {
            int r = f >> 3;
            int c = (f & 7) * 4;
            float4 v = make_float4(0.f, 0.f, 0.f, 0.f);
            int row = rowBase + r;
            if (row < N_NODES)
                v = *(const float4*)(x + (size_t)row * D_IN + k0 + c);
            xs[r][c + 0] = v.x; xs[r][c + 1] = v.y;
            xs[r][c + 2] = v.z; xs[r][c + 3] = v.w;
        }
        // load W,R tiles 32x128 (1024 float4 each -> 4 per thread)
#pragma unroll
        for (int f = tid; f < BK * D_OUT / 4; f += 256) {
            int r = f >> 5;
            int c = (f & 31) * 4;
            *(float4*)&ws[r][c] = *(const float4*)(W  + (size_t)(k0 + r) * D_OUT + c);
            *(float4*)&rs[r][c] = *(const float4*)(Rw + (size_t)(k0 + r) * D_OUT + c);
        }
        __syncthreads();

#pragma unroll 8
        for (int k = 0; k < BK; k++) {
            unsigned long long a2[4];
#pragma unroll
            for (int i = 0; i < 4; i++) a2[i] = dup2(xs[ty + 16 * i][k]);
            // conflict-free LDS.128: 16 distinct 32B-aligned addresses per warp
            ulonglong2 w0 = *(const ulonglong2*)&ws[k][tx * 8];
            ulonglong2 w1 = *(const ulonglong2*)&ws[k][tx * 8 + 4];
            ulonglong2 r0 = *(const ulonglong2*)&rs[k][tx * 8];
            ulonglong2 r1 = *(const ulonglong2*)&rs[k][tx * 8 + 4];
#pragma unroll
            for (int i = 0; i < 4; i++) {
                fma2(accW[i][0], a2[i], w0.x);
                fma2(accW[i][1], a2[i], w0.y);
                fma2(accW[i][2], a2[i], w1.x);
                fma2(accW[i][3], a2[i], w1.y);
                fma2(accR[i][0], a2[i], r0.x);
                fma2(accR[i][1], a2[i], r0.y);
                fma2(accR[i][2], a2[i], r1.x);
                fma2(accR[i][3], a2[i], r1.y);
            }
        }
        __syncthreads();
    }

    // epilogue
    const float4 b0  = *(const float4*)(bias + tx * 8);
    const float4 b1  = *(const float4*)(bias + tx * 8 + 4);
    const float4 rb0 = *(const float4*)(resb + tx * 8);
    const float4 rb1 = *(const float4*)(resb + tx * 8 + 4);
#pragma unroll
    for (int i = 0; i < 4; i++) {
        int row = rowBase + ty + 16 * i;
        if (row >= N_NODES) continue;
        float2 s0 = unpack2(accW[i][0]), s1 = unpack2(accW[i][1]);
        float2 s2 = unpack2(accW[i][2]), s3 = unpack2(accW[i][3]);
        float2 t0 = unpack2(accR[i][0]), t1 = unpack2(accR[i][1]);
        float2 t2 = unpack2(accR[i][2]), t3 = unpack2(accR[i][3]);

        float* supp = g_support + (size_t)row * D_OUT + tx * 8;
        *(float4*)(supp)     = make_float4(s0.x, s0.y, s1.x, s1.y);
        *(float4*)(supp + 4) = make_float4(s2.x, s2.y, s3.x, s3.y);

        float* bp = g_base + (size_t)row * D_OUT + tx * 8;
        float4 bv0, bv1;
        bv0.x = b0.x + fmaxf(t0.x + rb0.x, 0.f);
        bv0.y = b0.y + fmaxf(t0.y + rb0.y, 0.f);
        bv0.z = b0.z + fmaxf(t1.x + rb0.z, 0.f);
        bv0.w = b0.w + fmaxf(t1.y + rb0.w, 0.f);
        bv1.x = b1.x + fmaxf(t2.x + rb1.x, 0.f);
        bv1.y = b1.y + fmaxf(t2.y + rb1.y, 0.f);
        bv1.z = b1.z + fmaxf(t3.x + rb1.z, 0.f);
        bv1.w = b1.w + fmaxf(t3.y + rb1.w, 0.f);
        *(float4*)(bp)     = bv0;
        *(float4*)(bp + 4) = bv1;
    }
}

// ---------------- counting sort pipeline ----------------
__global__ void k_zero_count() {
    int i = blockIdx.x * blockDim.x + threadIdx.x;
    if (i < N_NODES) g_count[i] = 0;
}

__global__ void k_hist(const int* __restrict__ dst) {
    int e = blockIdx.x * blockDim.x + threadIdx.x;
    if (e < N_EDGES) atomicAdd(&g_count[dst[e]], 1);
}

__global__ void k_scan1() {  // per-block exclusive scan, 98 blocks x 1024
    __shared__ int s[1024];
    int i = blockIdx.x * 1024 + threadIdx.x;
    int v = (i < N_NODES) ? g_count[i] : 0;
    s[threadIdx.x] = v;
    __syncthreads();
#pragma unroll
    for (int off = 1; off < 1024; off <<= 1) {
        int t = (threadIdx.x >= off) ? s[threadIdx.x - off] : 0;
        __syncthreads();
        s[threadIdx.x] += t;
        __syncthreads();
    }
    if (i < N_NODES) g_offsets[i] = s[threadIdx.x] - v;   // exclusive
    if (threadIdx.x == 1023) g_partials[blockIdx.x] = s[1023];
}

__global__ void k_scan2() {  // single block scans 98 partials (128 threads)
    __shared__ int s[128];
    int nblk = (N_NODES + 1023) / 1024;   // 98
    int v = (threadIdx.x < nblk) ? g_partials[threadIdx.x] : 0;
    s[threadIdx.x] = v;
    __syncthreads();
#pragma unroll
    for (int off = 1; off < 128; off <<= 1) {
        int t = (threadIdx.x >= off) ? s[threadIdx.x - off] : 0;
        __syncthreads();
        s[threadIdx.x] += t;
        __syncthreads();
    }
    g_partials[threadIdx.x] = s[threadIdx.x] - v;         // exclusive
}

__global__ void k_scan3() {  // add block prefixes; init cursor
    int i = blockIdx.x * 1024 + threadIdx.x;
    if (i < N_NODES) {
        int o = g_offsets[i] + g_partials[blockIdx.x];
        g_offsets[i] = o;
        g_cursor[i]  = o;
    }
}

__global__ void k_scatter(const int* __restrict__ dst) {
    int e = blockIdx.x * blockDim.x + threadIdx.x;
    if (e < N_EDGES) {
        int d = dst[e];
        int p = atomicAdd(&g_cursor[d], 1);
        g_perm[p] = e;
    }
}

// ---------------- kernel: gather-aggregate + residual + LayerNorm ----------------
// one warp per node, 4 features per lane (float4)
__global__ void __launch_bounds__(256)
k_agg(const int* __restrict__ esrc, const float* __restrict__ ew,
      const float* __restrict__ gamma, const float* __restrict__ beta,
      float* __restrict__ out) {
    int gwarp = (blockIdx.x * blockDim.x + threadIdx.x) >> 5;
    int lane  = threadIdx.x & 31;
    if (gwarp >= N_NODES) return;
    const int n = gwarp;

    const int start = g_offsets[n];
    const int end   = (n == N_NODES - 1) ? N_EDGES : g_offsets[n + 1];

    const float4* __restrict__ sup4 = (const float4*)g_support;
    float4 acc = ((const float4*)g_base)[(size_t)n * 32 + lane];

    for (int b = start; b < end; b += 32) {
        int e = b + lane;
        int s = 0; float w = 0.f;
        if (e < end) {
            int idx = g_perm[e];
            s = esrc[idx];
            w = ew[idx];
        }
        int cnt = min(32, end - b);
        if (cnt == 32) {
#pragma unroll 8
            for (int it = 0; it < 32; it++) {
                int   ss = __shfl_sync(0xffffffffu, s, it);
                float ww = __shfl_sync(0xffffffffu, w, it);
                float4 v = sup4[(size_t)ss * 32 + lane];
                acc.x = fmaf(ww, v.x, acc.x);
                acc.y = fmaf(ww, v.y, acc.y);
                acc.z = fmaf(ww, v.z, acc.z);
                acc.w = fmaf(ww, v.w, acc.w);
            }
        } else {
            for (int it = 0; it < cnt; it++) {
                int   ss = __shfl_sync(0xffffffffu, s, it);
                float ww = __shfl_sync(0xffffffffu, w, it);
                float4 v = sup4[(size_t)ss * 32 + lane];
                acc.x = fmaf(ww, v.x, acc.x);
                acc.y = fmaf(ww, v.y, acc.y);
                acc.z = fmaf(ww, v.z, acc.z);
                acc.w = fmaf(ww, v.w, acc.w);
            }
        }
    }

    // LayerNorm over 128 features (warp reduction)
    float psum = acc.x + acc.y + acc.z + acc.w;
#pragma unroll
    for (int o = 16; o; o >>= 1) psum += __shfl_xor_sync(0xffffffffu, psum, o);
    float mu = psum * (1.f / 128.f);

    float dx = acc.x - mu, dy = acc.y - mu, dz = acc.z - mu, dw = acc.w - mu;
    float pv = dx * dx + dy * dy + dz * dz + dw * dw;
#pragma unroll
    for (int o = 16; o; o >>= 1) pv += __shfl_xor_sync(0xffffffffu, pv, o);
    float rstd = rsqrtf(pv * (1.f / 128.f) + LN_EPS);

    float4 g  = ((const float4*)gamma)[lane];
    float4 bt = ((const float4*)beta)[lane];
    float4 o4;
    o4.x = dx * rstd * g.x + bt.x;
    o4.y = dy * rstd * g.y + bt.y;
    o4.z = dz * rstd * g.z + bt.z;
    o4.w = dw * rstd * g.w + bt.w;
    ((float4*)out)[(size_t)n * 32 + lane] = o4;
}

// ---------------- launcher ----------------
extern "C" void kernel_launch(void* const* d_in, const int* in_sizes, int n_in,
                              void* d_out, int out_size) {
    const float* x      = (const float*)d_in[0];
    const float* weight = (const float*)d_in[1];
    const float* bias   = (const float*)d_in[2];
    const float* res_w  = (const float*)d_in[3];
    const float* res_b  = (const float*)d_in[4];
    const float* gamma  = (const float*)d_in[5];
    const float* beta   = (const float*)d_in[6];
    const float* ew     = (const float*)d_in[7];
    const int*   eidx   = (const int*)d_in[8];
    const int* esrc = eidx;
    const int* edst = eidx + N_EDGES;
    float* out = (float*)d_out;

    const int nScanBlk = (N_NODES + 1023) / 1024;   // 98

    k_zero_count<<<(N_NODES + 1023) / 1024, 1024>>>();
    k_gemm<<<(N_NODES + BM - 1) / BM, 256>>>(x, weight, res_w, bias, res_b);
    k_hist<<<(N_EDGES + 255) / 256, 256>>>(edst);
    k_scan1<<<nScanBlk, 1024>>>();
    k_scan2<<<1, 128>>>();
    k_scan3<<<nScanBlk, 1024>>>();
    k_scatter<<<(N_EDGES + 255) / 256, 256>>>(edst);
    k_agg<<<(N_NODES * 32 + 255) / 256, 256>>>(esrc, ew, gamma, beta, out);
}

// round 14
// speedup vs baseline: 1.5144x; 1.0001x over previous
#include <cuda_runtime.h>

#define N_NODES 100000
#define N_EDGES 3200000
#define D_IN    256
#define D_OUT   128
#define LN_EPS  1e-5f

#define BM 64
#define BK 32

// ---------------- static device scratch (no runtime allocation) ----------------
__device__ float g_support[(size_t)N_NODES * D_OUT];   // x @ W
__device__ float g_base[(size_t)N_NODES * D_OUT];      // bias + relu(x @ res_w + res_b)
__device__ int   g_count[N_NODES];
__device__ int   g_offsets[N_NODES];
__device__ int   g_cursor[N_NODES];
__device__ int   g_perm[N_EDGES];
__device__ int   g_partials[128];

// ---------------- f32x2 packed-math helpers (FFMA2 path) ----------------
__device__ __forceinline__ unsigned long long dup2(float a) {
    unsigned long long r;
    unsigned int ai = __float_as_uint(a);
    asm("mov.b64 %0, {%1, %1};" : "=l"(r) : "r"(ai));
    return r;
}
__device__ __forceinline__ void fma2(unsigned long long& d, unsigned long long a,
                                     unsigned long long b) {
    asm("fma.rn.f32x2 %0, %1, %2, %0;" : "+l"(d) : "l"(a), "l"(b));
}
__device__ __forceinline__ float2 unpack2(unsigned long long v) {
    unsigned int lo, hi;
    asm("mov.b64 {%0, %1}, %2;" : "=r"(lo), "=r"(hi) : "l"(v));
    float2 r;
    r.x = __uint_as_float(lo);
    r.y = __uint_as_float(hi);
    return r;
}

// ---------------- kernel 1: fused dual GEMM ----------------
// support[n,:] = x[n,:] @ W          (D_IN x D_OUT)
// base[n,:]    = bias + relu(x[n,:] @ Rw + resb)
__global__ void __launch_bounds__(256, 2)
k_gemm(const float* __restrict__ x, const float* __restrict__ W,
       const float* __restrict__ Rw, const float* __restrict__ bias,
       const float* __restrict__ resb) {
    __shared__ float xs[BM][BK + 1];
    __shared__ __align__(16) float ws[BK][D_OUT];
    __shared__ __align__(16) float rs[BK][D_OUT];

    const int tid = threadIdx.x;          // 256 threads
    const int tx  = tid & 15;             // column group: cols tx*8 .. tx*8+7
    const int ty  = tid >> 4;             // rows ty + 16*i, i=0..3
    const int rowBase = blockIdx.x * BM;

    unsigned long long accW[4][4], accR[4][4];
#pragma unroll
    for (int i = 0; i < 4; i++)
#pragma unroll
        for (int j = 0; j < 4; j++) { accW[i][j] = 0ull; accR[i][j] = 0ull; }

    for (int k0 = 0; k0 < D_IN; k0 += BK) {
        // load x tile 64x32 (512 float4 -> 2 per thread), guard tail rows
#pragma unroll
        for (int f = tid; f < BM * BK / 4; f += 256) {
            int r = f >> 3;
            int c = (f & 7) * 4;
            float4 v = make_float4(0.f, 0.f, 0.f, 0.f);
            int row = rowBase + r;
            if (row < N_NODES)
                v = *(const float4*)(x + (size_t)row * D_IN + k0 + c);
            xs[r][c + 0] = v.x; xs[r][c + 1] = v.y;
            xs[r][c + 2] = v.z; xs[r][c + 3] = v.w;
        }
        // load W,R tiles 32x128 (1024 float4 each -> 4 per thread)
#pragma unroll
        for (int f = tid; f < BK * D_OUT / 4; f += 256) {
            int r = f >> 5;
            int c = (f & 31) * 4;
            *(float4*)&ws[r][c] = *(const float4*)(W  + (size_t)(k0 + r) * D_OUT + c);
            *(float4*)&rs[r][c] = *(const float4*)(Rw + (size_t)(k0 + r) * D_OUT + c);
        }
        __syncthreads();

#pragma unroll 8
        for (int k = 0; k < BK; k++) {
            unsigned long long a2[4];
#pragma unroll
            for (int i = 0; i < 4; i++) a2[i] = dup2(xs[ty + 16 * i][k]);
            // conflict-free LDS.128: 16 distinct 32B-aligned addresses per warp
            ulonglong2 w0 = *(const ulonglong2*)&ws[k][tx * 8];
            ulonglong2 w1 = *(const ulonglong2*)&ws[k][tx * 8 + 4];
            ulonglong2 r0 = *(const ulonglong2*)&rs[k][tx * 8];
            ulonglong2 r1 = *(const ulonglong2*)&rs[k][tx * 8 + 4];
#pragma unroll
            for (int i = 0; i < 4; i++) {
                fma2(accW[i][0], a2[i], w0.x);
                fma2(accW[i][1], a2[i], w0.y);
                fma2(accW[i][2], a2[i], w1.x);
                fma2(accW[i][3], a2[i], w1.y);
                fma2(accR[i][0], a2[i], r0.x);
                fma2(accR[i][1], a2[i], r0.y);
                fma2(accR[i][2], a2[i], r1.x);
                fma2(accR[i][3], a2[i], r1.y);
            }
        }
        __syncthreads();
    }

    // epilogue
    const float4 b0  = *(const float4*)(bias + tx * 8);
    const float4 b1  = *(const float4*)(bias + tx * 8 + 4);
    const float4 rb0 = *(const float4*)(resb + tx * 8);
    const float4 rb1 = *(const float4*)(resb + tx * 8 + 4);
#pragma unroll
    for (int i = 0; i < 4; i++) {
        int row = rowBase + ty + 16 * i;
        if (row >= N_NODES) continue;
        float2 s0 = unpack2(accW[i][0]), s1 = unpack2(accW[i][1]);
        float2 s2 = unpack2(accW[i][2]), s3 = unpack2(accW[i][3]);
        float2 t0 = unpack2(accR[i][0]), t1 = unpack2(accR[i][1]);
        float2 t2 = unpack2(accR[i][2]), t3 = unpack2(accR[i][3]);

        float* supp = g_support + (size_t)row * D_OUT + tx * 8;
        *(float4*)(supp)     = make_float4(s0.x, s0.y, s1.x, s1.y);
        *(float4*)(supp + 4) = make_float4(s2.x, s2.y, s3.x, s3.y);

        float* bp = g_base + (size_t)row * D_OUT + tx * 8;
        float4 bv0, bv1;
        bv0.x = b0.x + fmaxf(t0.x + rb0.x, 0.f);
        bv0.y = b0.y + fmaxf(t0.y + rb0.y, 0.f);
        bv0.z = b0.z + fmaxf(t1.x + rb0.z, 0.f);
        bv0.w = b0.w + fmaxf(t1.y + rb0.w, 0.f);
        bv1.x = b1.x + fmaxf(t2.x + rb1.x, 0.f);
        bv1.y = b1.y + fmaxf(t2.y + rb1.y, 0.f);
        bv1.z = b1.z + fmaxf(t3.x + rb1.z, 0.f);
        bv1.w = b1.w + fmaxf(t3.y + rb1.w, 0.f);
        *(float4*)(bp)     = bv0;
        *(float4*)(bp + 4) = bv1;
    }
}

// ---------------- counting sort pipeline ----------------
__global__ void k_zero_count() {
    int i = blockIdx.x * blockDim.x + threadIdx.x;
    if (i < N_NODES) g_count[i] = 0;
}

__global__ void k_hist(const int* __restrict__ dst) {
    int e = blockIdx.x * blockDim.x + threadIdx.x;
    if (e < N_EDGES) atomicAdd(&g_count[dst[e]], 1);
}

__global__ void k_scan1() {  // per-block exclusive scan, 98 blocks x 1024
    __shared__ int s[1024];
    int i = blockIdx.x * 1024 + threadIdx.x;
    int v = (i < N_NODES) ? g_count[i] : 0;
    s[threadIdx.x] = v;
    __syncthreads();
#pragma unroll
    for (int off = 1; off < 1024; off <<= 1) {
        int t = (threadIdx.x >= off) ? s[threadIdx.x - off] : 0;
        __syncthreads();
        s[threadIdx.x] += t;
        __syncthreads();
    }
    if (i < N_NODES) g_offsets[i] = s[threadIdx.x] - v;   // exclusive
    if (threadIdx.x == 1023) g_partials[blockIdx.x] = s[1023];
}

__global__ void k_scan2() {  // single block scans 98 partials (128 threads)
    __shared__ int s[128];
    int nblk = (N_NODES + 1023) / 1024;   // 98
    int v = (threadIdx.x < nblk) ? g_partials[threadIdx.x] : 0;
    s[threadIdx.x] = v;
    __syncthreads();
#pragma unroll
    for (int off = 1; off < 128; off <<= 1) {
        int t = (threadIdx.x >= off) ? s[threadIdx.x - off] : 0;
        __syncthreads();
        s[threadIdx.x] += t;
        __syncthreads();
    }
    g_partials[threadIdx.x] = s[threadIdx.x] - v;         // exclusive
}

__global__ void k_scan3() {  // add block prefixes; init cursor
    int i = blockIdx.x * 1024 + threadIdx.x;
    if (i < N_NODES) {
        int o = g_offsets[i] + g_partials[blockIdx.x];
        g_offsets[i] = o;
        g_cursor[i]  = o;
    }
}

__global__ void k_scatter(const int* __restrict__ dst) {
    int e = blockIdx.x * blockDim.x + threadIdx.x;
    if (e < N_EDGES) {
        int d = dst[e];
        int p = atomicAdd(&g_cursor[d], 1);
        g_perm[p] = e;
    }
}

// ---------------- kernel: gather-aggregate + residual + LayerNorm ----------------
// one warp per node, 4 features per lane (float4)
__global__ void __launch_bounds__(256)
k_agg(const int* __restrict__ esrc, const float* __restrict__ ew,
      const float* __restrict__ gamma, const float* __restrict__ beta,
      float* __restrict__ out) {
    int gwarp = (blockIdx.x * blockDim.x + threadIdx.x) >> 5;
    int lane  = threadIdx.x & 31;
    if (gwarp >= N_NODES) return;
    const int n = gwarp;

    const int start = g_offsets[n];
    const int end   = (n == N_NODES - 1) ? N_EDGES : g_offsets[n + 1];

    const float4* __restrict__ sup4 = (const float4*)g_support;
    float4 acc = ((const float4*)g_base)[(size_t)n * 32 + lane];

    for (int b = start; b < end; b += 32) {
        int e = b + lane;
        int s = 0; float w = 0.f;
        if (e < end) {
            int idx = g_perm[e];
            s = esrc[idx];
            w = ew[idx];
        }
        int cnt = min(32, end - b);
        if (cnt == 32) {
#pragma unroll 8
            for (int it = 0; it < 32; it++) {
                int   ss = __shfl_sync(0xffffffffu, s, it);
                float ww = __shfl_sync(0xffffffffu, w, it);
                float4 v = sup4[(size_t)ss * 32 + lane];
                acc.x = fmaf(ww, v.x, acc.x);
                acc.y = fmaf(ww, v.y, acc.y);
                acc.z = fmaf(ww, v.z, acc.z);
                acc.w = fmaf(ww, v.w, acc.w);
            }
        } else {
            for (int it = 0; it < cnt; it++) {
                int   ss = __shfl_sync(0xffffffffu, s, it);
                float ww = __shfl_sync(0xffffffffu, w, it);
                float4 v = sup4[(size_t)ss * 32 + lane];
                acc.x = fmaf(ww, v.x, acc.x);
                acc.y = fmaf(ww, v.y, acc.y);
                acc.z = fmaf(ww, v.z, acc.z);
                acc.w = fmaf(ww, v.w, acc.w);
            }
        }
    }

    // LayerNorm over 128 features (warp reduction)
    float psum = acc.x + acc.y + acc.z + acc.w;
#pragma unroll
    for (int o = 16; o; o >>= 1) psum += __shfl_xor_sync(0xffffffffu, psum, o);
    float mu = psum * (1.f / 128.f);

    float dx = acc.x - mu, dy = acc.y - mu, dz = acc.z - mu, dw = acc.w - mu;
    float pv = dx * dx + dy * dy + dz * dz + dw * dw;
#pragma unroll
    for (int o = 16; o; o >>= 1) pv += __shfl_xor_sync(0xffffffffu, pv, o);
    float rstd = rsqrtf(pv * (1.f / 128.f) + LN_EPS);

    float4 g  = ((const float4*)gamma)[lane];
    float4 bt = ((const float4*)beta)[lane];
    float4 o4;
    o4.x = dx * rstd * g.x + bt.x;
    o4.y = dy * rstd * g.y + bt.y;
    o4.z = dz * rstd * g.z + bt.z;
    o4.w = dw * rstd * g.w + bt.w;
    ((float4*)out)[(size_t)n * 32 + lane] = o4;
}

// ---------------- launcher ----------------
extern "C" void kernel_launch(void* const* d_in, const int* in_sizes, int n_in,
                              void* d_out, int out_size) {
    const float* x      = (const float*)d_in[0];
    const float* weight = (const float*)d_in[1];
    const float* bias   = (const float*)d_in[2];
    const float* res_w  = (const float*)d_in[3];
    const float* res_b  = (const float*)d_in[4];
    const float* gamma  = (const float*)d_in[5];
    const float* beta   = (const float*)d_in[6];
    const float* ew     = (const float*)d_in[7];
    const int*   eidx   = (const int*)d_in[8];
    const int* esrc = eidx;
    const int* edst = eidx + N_EDGES;
    float* out = (float*)d_out;

    const int nScanBlk = (N_NODES + 1023) / 1024;   // 98

    k_zero_count<<<(N_NODES + 1023) / 1024, 1024>>>();
    k_gemm<<<(N_NODES + BM - 1) / BM, 256>>>(x, weight, res_w, bias, res_b);
    k_hist<<<(N_EDGES + 255) / 256, 256>>>(edst);
    k_scan1<<<nScanBlk, 1024>>>();
    k_scan2<<<1, 128>>>();
    k_scan3<<<nScanBlk, 1024>>>();
    k_scatter<<<(N_EDGES + 255) / 256, 256>>>(edst);
    k_agg<<<(N_NODES * 32 + 255) / 256, 256>>>(esrc, ew, gamma, beta, out);
}

// round 15
// speedup vs baseline: 1.5151x; 1.0005x over previous
#include <cuda_runtime.h>

#define N_NODES 100000
#define N_EDGES 3200000
#define D_IN    256
#define D_OUT   128
#define LN_EPS  1e-5f

#define BM 64
#define BK 32

// ---------------- static device scratch (no runtime allocation) ----------------
__device__ float g_support[(size_t)N_NODES * D_OUT];   // x @ W
__device__ float g_base[(size_t)N_NODES * D_OUT];      // bias + relu(x @ res_w + res_b)
__device__ int   g_count[N_NODES];
__device__ int   g_offsets[N_NODES];
__device__ int   g_cursor[N_NODES];
__device__ int   g_perm[N_EDGES];
__device__ int   g_partials[128];

// ---------------- f32x2 packed-math helpers (FFMA2 path) ----------------
__device__ __forceinline__ unsigned long long dup2(float a) {
    unsigned long long r;
    unsigned int ai = __float_as_uint(a);
    asm("mov.b64 %0, {%1, %1};" : "=l"(r) : "r"(ai));
    return r;
}
__device__ __forceinline__ void fma2(unsigned long long& d, unsigned long long a,
                                     unsigned long long b) {
    asm("fma.rn.f32x2 %0, %1, %2, %0;" : "+l"(d) : "l"(a), "l"(b));
}
__device__ __forceinline__ float2 unpack2(unsigned long long v) {
    unsigned int lo, hi;
    asm("mov.b64 {%0, %1}, %2;" : "=r"(lo), "=r"(hi) : "l"(v));
    float2 r;
    r.x = __uint_as_float(lo);
    r.y = __uint_as_float(hi);
    return r;
}

// ---------------- kernel 1: fused dual GEMM ----------------
// support[n,:] = x[n,:] @ W          (D_IN x D_OUT)
// base[n,:]    = bias + relu(x[n,:] @ Rw + resb)
__global__ void __launch_bounds__(256, 2)
k_gemm(const float* __restrict__ x, const float* __restrict__ W,
       const float* __restrict__ Rw, const float* __restrict__ bias,
       const float* __restrict__ resb) {
    __shared__ float xs[BM][BK + 1];
    __shared__ __align__(16) float ws[BK][D_OUT];
    __shared__ __align__(16) float rs[BK][D_OUT];

    const int tid = threadIdx.x;          // 256 threads
    const int tx  = tid & 15;             // column group: cols tx*8 .. tx*8+7
    const int ty  = tid >> 4;             // rows ty + 16*i, i=0..3
    const int rowBase = blockIdx.x * BM;

    unsigned long long accW[4][4], accR[4][4];
#pragma unroll
    for (int i = 0; i < 4; i++)
#pragma unroll
        for (int j = 0; j < 4; j++) { accW[i][j] = 0ull; accR[i][j] = 0ull; }

    for (int k0 = 0; k0 < D_IN; k0 += BK) {
        // load x tile 64x32 (512 float4 -> 2 per thread), guard tail rows
#pragma unroll
        for (int f = tid; f < BM * BK / 4; f += 256) {
            int r = f >> 3;
            int c = (f & 7) * 4;
            float4 v = make_float4(0.f, 0.f, 0.f, 0.f);
            int row = rowBase + r;
            if (row < N_NODES)
                v = *(const float4*)(x + (size_t)row * D_IN + k0 + c);
            xs[r][c + 0] = v.x; xs[r][c + 1] = v.y;
            xs[r][c + 2] = v.z; xs[r][c + 3] = v.w;
        }
        // load W,R tiles 32x128 (1024 float4 each -> 4 per thread)
#pragma unroll
        for (int f = tid; f < BK * D_OUT / 4; f += 256) {
            int r = f >> 5;
            int c = (f & 31) * 4;
            *(float4*)&ws[r][c] = *(const float4*)(W  + (size_t)(k0 + r) * D_OUT + c);
            *(float4*)&rs[r][c] = *(const float4*)(Rw + (size_t)(k0 + r) * D_OUT + c);
        }
        __syncthreads();

#pragma unroll 8
        for (int k = 0; k < BK; k++) {
            unsigned long long a2[4];
#pragma unroll
            for (int i = 0; i < 4; i++) a2[i] = dup2(xs[ty + 16 * i][k]);
            // conflict-free LDS.128: 16 distinct 32B-aligned addresses per warp
            ulonglong2 w0 = *(const ulonglong2*)&ws[k][tx * 8];
            ulonglong2 w1 = *(const ulonglong2*)&ws[k][tx * 8 + 4];
            ulonglong2 r0 = *(const ulonglong2*)&rs[k][tx * 8];
            ulonglong2 r1 = *(const ulonglong2*)&rs[k][tx * 8 + 4];
#pragma unroll
            for (int i = 0; i < 4; i++) {
                fma2(accW[i][0], a2[i], w0.x);
                fma2(accW[i][1], a2[i], w0.y);
                fma2(accW[i][2], a2[i], w1.x);
                fma2(accW[i][3], a2[i], w1.y);
                fma2(accR[i][0], a2[i], r0.x);
                fma2(accR[i][1], a2[i], r0.y);
                fma2(accR[i][2], a2[i], r1.x);
                fma2(accR[i][3], a2[i], r1.y);
            }
        }
        __syncthreads();
    }

    // epilogue
    const float4 b0  = *(const float4*)(bias + tx * 8);
    const float4 b1  = *(const float4*)(bias + tx * 8 + 4);
    const float4 rb0 = *(const float4*)(resb + tx * 8);
    const float4 rb1 = *(const float4*)(resb + tx * 8 + 4);
#pragma unroll
    for (int i = 0; i < 4; i++) {
        int row = rowBase + ty + 16 * i;
        if (row >= N_NODES) continue;
        float2 s0 = unpack2(accW[i][0]), s1 = unpack2(accW[i][1]);
        float2 s2 = unpack2(accW[i][2]), s3 = unpack2(accW[i][3]);
        float2 t0 = unpack2(accR[i][0]), t1 = unpack2(accR[i][1]);
        float2 t2 = unpack2(accR[i][2]), t3 = unpack2(accR[i][3]);

        float* supp = g_support + (size_t)row * D_OUT + tx * 8;
        *(float4*)(supp)     = make_float4(s0.x, s0.y, s1.x, s1.y);
        *(float4*)(supp + 4) = make_float4(s2.x, s2.y, s3.x, s3.y);

        float* bp = g_base + (size_t)row * D_OUT + tx * 8;
        float4 bv0, bv1;
        bv0.x = b0.x + fmaxf(t0.x + rb0.x, 0.f);
        bv0.y = b0.y + fmaxf(t0.y + rb0.y, 0.f);
        bv0.z = b0.z + fmaxf(t1.x + rb0.z, 0.f);
        bv0.w = b0.w + fmaxf(t1.y + rb0.w, 0.f);
        bv1.x = b1.x + fmaxf(t2.x + rb1.x, 0.f);
        bv1.y = b1.y + fmaxf(t2.y + rb1.y, 0.f);
        bv1.z = b1.z + fmaxf(t3.x + rb1.z, 0.f);
        bv1.w = b1.w + fmaxf(t3.y + rb1.w, 0.f);
        *(float4*)(bp)     = bv0;
        *(float4*)(bp + 4) = bv1;
    }
}

// ---------------- counting sort pipeline ----------------
__global__ void k_zero_count() {
    int i = blockIdx.x * blockDim.x + threadIdx.x;
    if (i < N_NODES) g_count[i] = 0;
}

__global__ void k_hist(const int* __restrict__ dst) {
    int e = blockIdx.x * blockDim.x + threadIdx.x;
    if (e < N_EDGES) atomicAdd(&g_count[dst[e]], 1);
}

__global__ void k_scan1() {  // per-block exclusive scan, 98 blocks x 1024
    __shared__ int s[1024];
    int i = blockIdx.x * 1024 + threadIdx.x;
    int v = (i < N_NODES) ? g_count[i] : 0;
    s[threadIdx.x] = v;
    __syncthreads();
#pragma unroll
    for (int off = 1; off < 1024; off <<= 1) {
        int t = (threadIdx.x >= off) ? s[threadIdx.x - off] : 0;
        __syncthreads();
        s[threadIdx.x] += t;
        __syncthreads();
    }
    if (i < N_NODES) g_offsets[i] = s[threadIdx.x] - v;   // exclusive
    if (threadIdx.x == 1023) g_partials[blockIdx.x] = s[1023];
}

__global__ void k_scan2() {  // single block scans 98 partials (128 threads)
    __shared__ int s[128];
    int nblk = (N_NODES + 1023) / 1024;   // 98
    int v = (threadIdx.x < nblk) ? g_partials[threadIdx.x] : 0;
    s[threadIdx.x] = v;
    __syncthreads();
#pragma unroll
    for (int off = 1; off < 128; off <<= 1) {
        int t = (threadIdx.x >= off) ? s[threadIdx.x - off] : 0;
        __syncthreads();
        s[threadIdx.x] += t;
        __syncthreads();
    }
    g_partials[threadIdx.x] = s[threadIdx.x] - v;         // exclusive
}

__global__ void k_scan3() {  // add block prefixes; init cursor
    int i = blockIdx.x * 1024 + threadIdx.x;
    if (i < N_NODES) {
        int o = g_offsets[i] + g_partials[blockIdx.x];
        g_offsets[i] = o;
        g_cursor[i]  = o;
    }
}

__global__ void k_scatter(const int* __restrict__ dst) {
    int e = blockIdx.x * blockDim.x + threadIdx.x;
    if (e < N_EDGES) {
        int d = dst[e];
        int p = atomicAdd(&g_cursor[d], 1);
        g_perm[p] = e;
    }
}

// ---------------- kernel: gather-aggregate + residual + LayerNorm ----------------
// one warp per node, 4 features per lane (float4)
__global__ void __launch_bounds__(256)
k_agg(const int* __restrict__ esrc, const float* __restrict__ ew,
      const float* __restrict__ gamma, const float* __restrict__ beta,
      float* __restrict__ out) {
    int gwarp = (blockIdx.x * blockDim.x + threadIdx.x) >> 5;
    int lane  = threadIdx.x & 31;
    if (gwarp >= N_NODES) return;
    const int n = gwarp;

    const int start = g_offsets[n];
    const int end   = (n == N_NODES - 1) ? N_EDGES : g_offsets[n + 1];

    const float4* __restrict__ sup4 = (const float4*)g_support;
    float4 acc = ((const float4*)g_base)[(size_t)n * 32 + lane];

    for (int b = start; b < end; b += 32) {
        int e = b + lane;
        int s = 0; float w = 0.f;
        if (e < end) {
            int idx = g_perm[e];
            s = esrc[idx];
            w = ew[idx];
        }
        int cnt = min(32, end - b);
        if (cnt == 32) {
#pragma unroll 8
            for (int it = 0; it < 32; it++) {
                int   ss = __shfl_sync(0xffffffffu, s, it);
                float ww = __shfl_sync(0xffffffffu, w, it);
                float4 v = sup4[(size_t)ss * 32 + lane];
                acc.x = fmaf(ww, v.x, acc.x);
                acc.y = fmaf(ww, v.y, acc.y);
                acc.z = fmaf(ww, v.z, acc.z);
                acc.w = fmaf(ww, v.w, acc.w);
            }
        } else {
            for (int it = 0; it < cnt; it++) {
                int   ss = __shfl_sync(0xffffffffu, s, it);
                float ww = __shfl_sync(0xffffffffu, w, it);
                float4 v = sup4[(size_t)ss * 32 + lane];
                acc.x = fmaf(ww, v.x, acc.x);
                acc.y = fmaf(ww, v.y, acc.y);
                acc.z = fmaf(ww, v.z, acc.z);
                acc.w = fmaf(ww, v.w, acc.w);
            }
        }
    }

    // LayerNorm over 128 features (warp reduction)
    float psum = acc.x + acc.y + acc.z + acc.w;
#pragma unroll
    for (int o = 16; o; o >>= 1) psum += __shfl_xor_sync(0xffffffffu, psum, o);
    float mu = psum * (1.f / 128.f);

    float dx = acc.x - mu, dy = acc.y - mu, dz = acc.z - mu, dw = acc.w - mu;
    float pv = dx * dx + dy * dy + dz * dz + dw * dw;
#pragma unroll
    for (int o = 16; o; o >>= 1) pv += __shfl_xor_sync(0xffffffffu, pv, o);
    float rstd = rsqrtf(pv * (1.f / 128.f) + LN_EPS);

    float4 g  = ((const float4*)gamma)[lane];
    float4 bt = ((const float4*)beta)[lane];
    float4 o4;
    o4.x = dx * rstd * g.x + bt.x;
    o4.y = dy * rstd * g.y + bt.y;
    o4.z = dz * rstd * g.z + bt.z;
    o4.w = dw * rstd * g.w + bt.w;
    ((float4*)out)[(size_t)n * 32 + lane] = o4;
}

// ---------------- launcher ----------------
extern "C" void kernel_launch(void* const* d_in, const int* in_sizes, int n_in,
                              void* d_out, int out_size) {
    const float* x      = (const float*)d_in[0];
    const float* weight = (const float*)d_in[1];
    const float* bias   = (const float*)d_in[2];
    const float* res_w  = (const float*)d_in[3];
    const float* res_b  = (const float*)d_in[4];
    const float* gamma  = (const float*)d_in[5];
    const float* beta   = (const float*)d_in[6];
    const float* ew     = (const float*)d_in[7];
    const int*   eidx   = (const int*)d_in[8];
    const int* esrc = eidx;
    const int* edst = eidx + N_EDGES;
    float* out = (float*)d_out;

    const int nScanBlk = (N_NODES + 1023) / 1024;   // 98

    k_zero_count<<<(N_NODES + 1023) / 1024, 1024>>>();
    k_gemm<<<(N_NODES + BM - 1) / BM, 256>>>(x, weight, res_w, bias, res_b);
    k_hist<<<(N_EDGES + 255) / 256, 256>>>(edst);
    k_scan1<<<nScanBlk, 1024>>>();
    k_scan2<<<1, 128>>>();
    k_scan3<<<nScanBlk, 1024>>>();
    k_scatter<<<(N_EDGES + 255) / 256, 256>>>(edst);
    k_agg<<<(N_NODES * 32 + 255) / 256, 256>>>(esrc, ew, gamma, beta, out);
}

// round 17
// speedup vs baseline: 3.0264x; 1.9974x over previous
#include <cuda_runtime.h>
#include <cuda_bf16.h>
#include <cstdint>

#define N_NODES 100000
#define N_EDGES 3200000
#define D_IN    256
#define D_OUT   128
#define LN_EPS  1e-5f

// ---------------- static device scratch (no runtime allocation) ----------------
__device__ float g_support[(size_t)N_NODES * D_OUT];   // x @ W
__device__ float g_base[(size_t)N_NODES * D_OUT];      // bias + relu(x @ res_w + res_b)
__device__ int   g_count[N_NODES];
__device__ int   g_offsets[N_NODES];
__device__ int   g_cursor[N_NODES];
__device__ unsigned long long g_pack[N_EDGES];         // packed (weight<<32 | src)
__device__ int   g_partials[128];
// pre-converted, pre-transposed, pre-swizzled B tiles:
// [mat: Whi,Wlo,Rhi,Rlo][kchunk 0..3][n=0..127 rows x kk=0..63 bf16, SW128 swizzled 128B rows]
__device__ __nv_bfloat16 g_Bc[4][4][128 * 64];

#define SWZ128(o) ((o) ^ (((o) >> 3) & 0x70))

__device__ __forceinline__ uint32_t smem_to_u32(const void* p) {
    uint32_t a;
    asm("{ .reg .u64 t; cvta.to.shared.u64 t, %1; cvt.u32.u64 %0, t; }" : "=r"(a) : "l"(p));
    return a;
}

__device__ __forceinline__ void ldsm4(unsigned* r, uint32_t addr) {
    asm volatile("ldmatrix.sync.aligned.m8n8.x4.shared.b16 {%0,%1,%2,%3}, [%4];"
                 : "=r"(r[0]), "=r"(r[1]), "=r"(r[2]), "=r"(r[3]) : "r"(addr));
}

__device__ __forceinline__ void mma16816(float* d, const unsigned* a, const unsigned* b) {
    asm volatile(
        "mma.sync.aligned.m16n8k16.row.col.f32.bf16.bf16.f32 "
        "{%0,%1,%2,%3}, {%4,%5,%6,%7}, {%8,%9}, {%0,%1,%2,%3};"
        : "+f"(d[0]), "+f"(d[1]), "+f"(d[2]), "+f"(d[3])
        : "r"(a[0]), "r"(a[1]), "r"(a[2]), "r"(a[3]), "r"(b[0]), "r"(b[1]));
}

__device__ __forceinline__ void cp16(uint32_t smem_dst, const void* gsrc) {
    asm volatile("cp.async.ca.shared.global [%0], [%1], 16;" :: "r"(smem_dst), "l"(gsrc));
}
#define CP_COMMIT() asm volatile("cp.async.commit_group;" ::: "memory")
#define CP_WAIT0()  asm volatile("cp.async.wait_group 0;" ::: "memory")

__device__ __forceinline__ void split2(float a, float b, unsigned& hi, unsigned& lo) {
    __nv_bfloat16 ha = __float2bfloat16(a);
    __nv_bfloat16 hb = __float2bfloat16(b);
    __nv_bfloat16 la = __float2bfloat16(a - __bfloat162float(ha));
    __nv_bfloat16 lb = __float2bfloat16(b - __bfloat162float(hb));
    hi = ((unsigned)__bfloat16_as_ushort(hb) << 16) | (unsigned)__bfloat16_as_ushort(ha);
    lo = ((unsigned)__bfloat16_as_ushort(lb) << 16) | (unsigned)__bfloat16_as_ushort(la);
}

// ---------------- kernel 0: pre-convert W/R into swizzled hi/lo bf16 B tiles ----------------
__global__ void k_prepB(const float* __restrict__ W, const float* __restrict__ Rw) {
    int idx = blockIdx.x * blockDim.x + threadIdx.x;   // 65536 = 2 * 256 * 128
    if (idx >= 2 * D_IN * D_OUT) return;
    int n = idx & 127;
    int k = (idx >> 7) & 255;
    int s = idx >> 15;                                  // 0 = W, 1 = R
    float v = (s ? Rw : W)[k * D_OUT + n];
    __nv_bfloat16 h = __float2bfloat16(v);
    __nv_bfloat16 l = __float2bfloat16(v - __bfloat162float(h));
    int ch = k >> 6, kk = k & 63;
    unsigned off = SWZ128((unsigned)(n * 128 + kk * 2)) >> 1;
    g_Bc[2 * s + 0][ch][off] = h;
    g_Bc[2 * s + 1][ch][off] = l;
}

// ---------------- kernel 1: mma.sync dual GEMM (bf16 hi/lo 3-pass, fp32 accum) ----------------
// smem: A hi [4ch][128x64] @0 (64KB), A lo @65536 (64KB), B double-buffered @131072 (2x32KB)
#define SM_A     0
#define SM_B     131072
#define SM_TOTAL 196608

__global__ void __launch_bounds__(256)
k_gemm_mma(const float* __restrict__ x, const float* __restrict__ bias,
           const float* __restrict__ resb) {
    extern __shared__ char smem[];
    const uint32_t sb = smem_to_u32(smem);
    const int tid  = threadIdx.x;
    const int wid  = tid >> 5;
    const int lane = tid & 31;
    const int wr   = wid >> 1;            // 0..3 : rows wr*32
    const int wc   = wid & 1;             // 0..1 : cols wc*64
    const int rowBase = blockIdx.x * 128;

    // issue B(mat0, ch0) into buf0 early
    {
        const char* src = (const char*)&g_Bc[0][0][0];   // Whi ch0; Wlo is g_Bc[1]
#pragma unroll
        for (int f = tid; f < 2048; f += 256) {
            int part = f >> 10, q = f & 1023;
            cp16(sb + SM_B + part * 16384 + q * 16,
                 (const char*)&g_Bc[part][0][0] + q * 16);
        }
        (void)src;
        CP_COMMIT();
    }

    // A: load x rows, split hi/lo, swizzled store (128 rows x 256 k)
#pragma unroll
    for (int f = tid; f < 128 * 64; f += 256) {          // f indexes float4s
        int r = f >> 6, q = f & 63;
        int c = q * 4;
        int ch = c >> 6, kk = c & 63;
        int row = rowBase + r;
        float4 v = make_float4(0.f, 0.f, 0.f, 0.f);
        if (row < N_NODES) v = *(const float4*)(x + (size_t)row * D_IN + c);
        unsigned h0, l0, h1, l1;
        split2(v.x, v.y, h0, l0);
        split2(v.z, v.w, h1, l1);
        uint32_t so = SWZ128((unsigned)(r * 128 + kk * 2));
        *(uint2*)(smem + SM_A + ch * 16384 + so)         = make_uint2(h0, h1);
        *(uint2*)(smem + SM_A + 65536 + ch * 16384 + so) = make_uint2(l0, l1);
    }

    // per-lane ldmatrix address components
    int aq = lane >> 3;
    int arow_in = (lane & 7) + 8 * (aq & 1);
    int akb = (aq >> 1) * 16;                 // byte offset within 32B k16 span
    uint32_t arowb[2];
#pragma unroll
    for (int mt = 0; mt < 2; mt++)
        arowb[mt] = (uint32_t)((wr * 32 + mt * 16 + arow_in) * 128 + akb);

    int bp = lane >> 3;
    int bn_in = (bp >> 1) * 8 + (lane & 7);
    int bkb = (bp & 1) * 16;
    uint32_t bnb[4];
#pragma unroll
    for (int ng = 0; ng < 4; ng++)
        bnb[ng] = (uint32_t)((wc * 64 + ng * 16 + bn_in) * 128 + bkb);

    float acc[2][8][4];
#pragma unroll
    for (int mt = 0; mt < 2; mt++)
#pragma unroll
        for (int nt = 0; nt < 8; nt++)
#pragma unroll
            for (int i = 0; i < 4; i++) acc[mt][nt][i] = 0.f;

    const int r_in = lane >> 2;
    const int cb   = (lane & 3) * 2;

    for (int it = 0; it < 8; it++) {
        const int mat = it >> 2, ch = it & 3, buf = it & 1;

        CP_WAIT0();
        __syncthreads();

        if (it < 7) {
            int nmat = (it + 1) >> 2, nch = (it + 1) & 3, nbuf = buf ^ 1;
#pragma unroll
            for (int f = tid; f < 2048; f += 256) {
                int part = f >> 10, q = f & 1023;
                cp16(sb + SM_B + nbuf * 32768 + part * 16384 + q * 16,
                     (const char*)&g_Bc[2 * nmat + part][nch][0] + q * 16);
            }
            CP_COMMIT();
        }

        const uint32_t aBaseH = sb + SM_A + ch * 16384;
        const uint32_t aBaseL = aBaseH + 65536;
        const uint32_t bBaseH = sb + SM_B + buf * 32768;
        const uint32_t bBaseL = bBaseH + 16384;

#pragma unroll
        for (int k16 = 0; k16 < 4; k16++) {
            const uint32_t kdelta = (uint32_t)(k16 * 32);
            unsigned aH[2][4], aL[2][4];
#pragma unroll
            for (int mt = 0; mt < 2; mt++) {
                uint32_t so = SWZ128(arowb[mt] + kdelta);
                ldsm4(aH[mt], aBaseH + so);
                ldsm4(aL[mt], aBaseL + so);
            }
            unsigned bH[4][4], bL[4][4];
#pragma unroll
            for (int ng = 0; ng < 4; ng++) {
                uint32_t so = SWZ128(bnb[ng] + kdelta);
                ldsm4(bH[ng], bBaseH + so);
                ldsm4(bL[ng], bBaseL + so);
            }
#pragma unroll
            for (int mt = 0; mt < 2; mt++)
#pragma unroll
                for (int nt = 0; nt < 8; nt++) {
                    const unsigned* bh = &bH[nt >> 1][(nt & 1) * 2];
                    const unsigned* bl = &bL[nt >> 1][(nt & 1) * 2];
                    mma16816(acc[mt][nt], aH[mt], bh);
                    mma16816(acc[mt][nt], aH[mt], bl);
                    mma16816(acc[mt][nt], aL[mt], bh);
                }
        }
        __syncthreads();   // compute done before next-iter overwrite of this buf

        if (ch == 3) {
            // epilogue for this matrix, then reset accumulators
#pragma unroll
            for (int nt = 0; nt < 8; nt++) {
                int c = wc * 64 + nt * 8 + cb;
                float2 bb = make_float2(0.f, 0.f), rr = make_float2(0.f, 0.f);
                if (mat) { bb = *(const float2*)(bias + c); rr = *(const float2*)(resb + c); }
#pragma unroll
                for (int mt = 0; mt < 2; mt++) {
                    int r0 = rowBase + wr * 32 + mt * 16 + r_in;
                    float2 v0 = make_float2(acc[mt][nt][0], acc[mt][nt][1]);
                    float2 v1 = make_float2(acc[mt][nt][2], acc[mt][nt][3]);
                    if (mat == 0) {
                        if (r0 < N_NODES)
                            *(float2*)(g_support + (size_t)r0 * D_OUT + c) = v0;
                        if (r0 + 8 < N_NODES)
                            *(float2*)(g_support + (size_t)(r0 + 8) * D_OUT + c) = v1;
                    } else {
                        float2 u0, u1;
                        u0.x = bb.x + fmaxf(v0.x + rr.x, 0.f);
                        u0.y = bb.y + fmaxf(v0.y + rr.y, 0.f);
                        u1.x = bb.x + fmaxf(v1.x + rr.x, 0.f);
                        u1.y = bb.y + fmaxf(v1.y + rr.y, 0.f);
                        if (r0 < N_NODES)
                            *(float2*)(g_base + (size_t)r0 * D_OUT + c) = u0;
                        if (r0 + 8 < N_NODES)
                            *(float2*)(g_base + (size_t)(r0 + 8) * D_OUT + c) = u1;
                    }
                    acc[mt][nt][0] = 0.f; acc[mt][nt][1] = 0.f;
                    acc[mt][nt][2] = 0.f; acc[mt][nt][3] = 0.f;
                }
            }
        }
    }
}

// ---------------- counting sort pipeline ----------------
__global__ void k_zero_count() {
    int i = blockIdx.x * blockDim.x + threadIdx.x;
    if (i < N_NODES) g_count[i] = 0;
}

__global__ void k_hist(const int* __restrict__ dst) {
    int e = blockIdx.x * blockDim.x + threadIdx.x;
    if (e < N_EDGES) atomicAdd(&g_count[dst[e]], 1);
}

__global__ void k_scan1() {
    __shared__ int s[1024];
    int i = blockIdx.x * 1024 + threadIdx.x;
    int v = (i < N_NODES) ? g_count[i] : 0;
    s[threadIdx.x] = v;
    __syncthreads();
#pragma unroll
    for (int off = 1; off < 1024; off <<= 1) {
        int t = (threadIdx.x >= off) ? s[threadIdx.x - off] : 0;
        __syncthreads();
        s[threadIdx.x] += t;
        __syncthreads();
    }
    if (i < N_NODES) g_offsets[i] = s[threadIdx.x] - v;
    if (threadIdx.x == 1023) g_partials[blockIdx.x] = s[1023];
}

__global__ void k_scan2() {
    __shared__ int s[128];
    int nblk = (N_NODES + 1023) / 1024;
    int v = (threadIdx.x < nblk) ? g_partials[threadIdx.x] : 0;
    s[threadIdx.x] = v;
    __syncthreads();
#pragma unroll
    for (int off = 1; off < 128; off <<= 1) {
        int t = (threadIdx.x >= off) ? s[threadIdx.x - off] : 0;
        __syncthreads();
        s[threadIdx.x] += t;
        __syncthreads();
    }
    g_partials[threadIdx.x] = s[threadIdx.x] - v;
}

__global__ void k_scan3() {
    int i = blockIdx.x * 1024 + threadIdx.x;
    if (i < N_NODES) {
        int o = g_offsets[i] + g_partials[blockIdx.x];
        g_offsets[i] = o;
        g_cursor[i]  = o;
    }
}

// scatter packed (src, weight) so aggregation reads edge meta sequentially
__global__ void k_scatter(const int* __restrict__ dst, const int* __restrict__ src,
                          const float* __restrict__ ew) {
    int e = blockIdx.x * blockDim.x + threadIdx.x;
    if (e < N_EDGES) {
        int d = dst[e];
        int p = atomicAdd(&g_cursor[d], 1);
        g_pack[p] = ((unsigned long long)__float_as_uint(ew[e]) << 32) | (unsigned)src[e];
    }
}

// ---------------- kernel: gather-aggregate + residual + LayerNorm ----------------
__global__ void __launch_bounds__(256)
k_agg(const float* __restrict__ gamma, const float* __restrict__ beta,
      float* __restrict__ out) {
    int gwarp = (blockIdx.x * blockDim.x + threadIdx.x) >> 5;
    int lane  = threadIdx.x & 31;
    if (gwarp >= N_NODES) return;
    const int n = gwarp;

    const int start = g_offsets[n];
    const int end   = (n == N_NODES - 1) ? N_EDGES : g_offsets[n + 1];

    const float4* __restrict__ sup4 = (const float4*)g_support;
    float4 acc = ((const float4*)g_base)[(size_t)n * 32 + lane];

    for (int b = start; b < end; b += 32) {
        int e = b + lane;
        int s = 0; float w = 0.f;
        if (e < end) {
            unsigned long long pk = g_pack[e];
            s = (int)(pk & 0xffffffffu);
            w = __uint_as_float((unsigned)(pk >> 32));
        }
        int cnt = min(32, end - b);
        if (cnt == 32) {
#pragma unroll 8
            for (int it = 0; it < 32; it++) {
                int   ss = __shfl_sync(0xffffffffu, s, it);
                float ww = __shfl_sync(0xffffffffu, w, it);
                float4 v = sup4[(size_t)ss * 32 + lane];
                acc.x = fmaf(ww, v.x, acc.x);
                acc.y = fmaf(ww, v.y, acc.y);
                acc.z = fmaf(ww, v.z, acc.z);
                acc.w = fmaf(ww, v.w, acc.w);
            }
        } else {
            for (int it = 0; it < cnt; it++) {
                int   ss = __shfl_sync(0xffffffffu, s, it);
                float ww = __shfl_sync(0xffffffffu, w, it);
                float4 v = sup4[(size_t)ss * 32 + lane];
                acc.x = fmaf(ww, v.x, acc.x);
                acc.y = fmaf(ww, v.y, acc.y);
                acc.z = fmaf(ww, v.z, acc.z);
                acc.w = fmaf(ww, v.w, acc.w);
            }
        }
    }

    float psum = acc.x + acc.y + acc.z + acc.w;
#pragma unroll
    for (int o = 16; o; o >>= 1) psum += __shfl_xor_sync(0xffffffffu, psum, o);
    float mu = psum * (1.f / 128.f);

    float dx = acc.x - mu, dy = acc.y - mu, dz = acc.z - mu, dw = acc.w - mu;
    float pv = dx * dx + dy * dy + dz * dz + dw * dw;
#pragma unroll
    for (int o = 16; o; o >>= 1) pv += __shfl_xor_sync(0xffffffffu, pv, o);
    float rstd = rsqrtf(pv * (1.f / 128.f) + LN_EPS);

    float4 g  = ((const float4*)gamma)[lane];
    float4 bt = ((const float4*)beta)[lane];
    float4 o4;
    o4.x = dx * rstd * g.x + bt.x;
    o4.y = dy * rstd * g.y + bt.y;
    o4.z = dz * rstd * g.z + bt.z;
    o4.w = dw * rstd * g.w + bt.w;
    ((float4*)out)[(size_t)n * 32 + lane] = o4;
}

// ---------------- launcher ----------------
extern "C" void kernel_launch(void* const* d_in, const int* in_sizes, int n_in,
                              void* d_out, int out_size) {
    const float* x      = (const float*)d_in[0];
    const float* weight = (const float*)d_in[1];
    const float* bias   = (const float*)d_in[2];
    const float* res_w  = (const float*)d_in[3];
    const float* res_b  = (const float*)d_in[4];
    const float* gamma  = (const float*)d_in[5];
    const float* beta   = (const float*)d_in[6];
    const float* ew     = (const float*)d_in[7];
    const int*   eidx   = (const int*)d_in[8];
    const int* esrc = eidx;
    const int* edst = eidx + N_EDGES;
    float* out = (float*)d_out;

    cudaFuncSetAttribute(k_gemm_mma, cudaFuncAttributeMaxDynamicSharedMemorySize, SM_TOTAL);

    const int nScanBlk = (N_NODES + 1023) / 1024;   // 98
    const int nGemmBlk = (N_NODES + 127) / 128;     // 782

    k_zero_count<<<(N_NODES + 1023) / 1024, 1024>>>();
    k_prepB<<<(2 * D_IN * D_OUT + 255) / 256, 256>>>(weight, res_w);
    k_gemm_mma<<<nGemmBlk, 256, SM_TOTAL>>>(x, bias, res_b);
    k_hist<<<(N_EDGES + 255) / 256, 256>>>(edst);
    k_scan1<<<nScanBlk, 1024>>>();
    k_scan2<<<1, 128>>>();
    k_scan3<<<nScanBlk, 1024>>>();
    k_scatter<<<(N_EDGES + 255) / 256, 256>>>(edst, esrc, ew);
    k_agg<<<(N_NODES * 32 + 255) / 256, 256>>>(gamma, beta, out);
}